// round 1
// baseline (speedup 1.0000x reference)
#include <cuda_runtime.h>
#include <cuda_bf16.h>

#define FEAT 64
#define EPR 64              // edges per row-group (16 threads)
#define ROWS_PER_BLOCK 16   // 256 threads / 16 lanes
#define THREADS 256

// out[n*64+f] = bias[f]
__global__ void init_out_kernel(float* __restrict__ out,
                                const float* __restrict__ bias,
                                int total) {
    int i = blockIdx.x * blockDim.x + threadIdx.x;
    int stride = gridDim.x * blockDim.x;
    for (; i < total; i += stride) {
        out[i] = bias[i & (FEAT - 1)];
    }
}

// Weighted segment-sum over sorted segment_ids.
// Each 16-thread row-group walks EPR consecutive edges; thread `lane` owns
// features [4*lane, 4*lane+4) as a float4 running accumulator, flushed via
// atomicAdd only when the segment id changes (or at chunk end).
__global__ void __launch_bounds__(THREADS)
segsum_kernel(const float4* __restrict__ feats,   // [E, 16] float4 view of [E,64] f32
              const float*  __restrict__ attn,    // [E]
              const int*    __restrict__ seg,     // [E] sorted
              float* __restrict__ out,            // [N, 64]
              int n_edges) {
    int row  = blockIdx.x * ROWS_PER_BLOCK + (threadIdx.x >> 4);
    int lane = threadIdx.x & 15;

    int e0 = row * EPR;
    if (e0 >= n_edges) return;
    int e_end = e0 + EPR;
    if (e_end > n_edges) e_end = n_edges;

    float4 acc = make_float4(0.f, 0.f, 0.f, 0.f);
    int cur = __ldg(&seg[e0]);

    #pragma unroll 4
    for (int e = e0; e < e_end; ++e) {
        int   s = __ldg(&seg[e]);
        float a = __ldg(&attn[e]);
        float4 f = __ldg(&feats[(long long)e * 16 + lane]);

        if (s != cur) {
            float* o = out + (long long)cur * FEAT + lane * 4;
            atomicAdd(o + 0, acc.x);
            atomicAdd(o + 1, acc.y);
            atomicAdd(o + 2, acc.z);
            atomicAdd(o + 3, acc.w);
            acc = make_float4(0.f, 0.f, 0.f, 0.f);
            cur = s;
        }
        acc.x = fmaf(a, f.x, acc.x);
        acc.y = fmaf(a, f.y, acc.y);
        acc.z = fmaf(a, f.z, acc.z);
        acc.w = fmaf(a, f.w, acc.w);
    }

    float* o = out + (long long)cur * FEAT + lane * 4;
    atomicAdd(o + 0, acc.x);
    atomicAdd(o + 1, acc.y);
    atomicAdd(o + 2, acc.z);
    atomicAdd(o + 3, acc.w);
}

extern "C" void kernel_launch(void* const* d_in, const int* in_sizes, int n_in,
                              void* d_out, int out_size) {
    // metadata order: nodes[0] (unused), neighbor_feats[1], attention[2],
    //                 bias[3], segment_ids[4]
    const float* feats = (const float*)d_in[1];
    const float* attn  = (const float*)d_in[2];
    const float* bias  = (const float*)d_in[3];
    const int*   seg   = (const int*)d_in[4];
    float* out = (float*)d_out;

    int n_edges = in_sizes[2];          // attention element count = E

    // 1) out = bias (broadcast)
    {
        int total = out_size;           // N * FEAT
        int blocks = (total + THREADS - 1) / THREADS;
        if (blocks > 4096) blocks = 4096;
        init_out_kernel<<<blocks, THREADS>>>(out, bias, total);
    }

    // 2) weighted segment-sum with boundary-only atomics
    {
        int n_rows = (n_edges + EPR - 1) / EPR;
        int blocks = (n_rows + ROWS_PER_BLOCK - 1) / ROWS_PER_BLOCK;
        segsum_kernel<<<blocks, THREADS>>>((const float4*)feats, attn, seg, out, n_edges);
    }
}

// round 4
// speedup vs baseline: 1.0047x; 1.0047x over previous
#include <cuda_runtime.h>
#include <cuda_bf16.h>

#define FEAT 64
#define EPR 64              // edges per row-group (16 lanes)
#define ROWS_PER_BLOCK 16   // 256 threads / 16 lanes
#define THREADS 256

// out = broadcast(bias), vectorized: out4[i] = bias4[i & 15]
__global__ void init_out_kernel(float4* __restrict__ out,
                                const float4* __restrict__ bias,
                                int total4) {
    int i = blockIdx.x * blockDim.x + threadIdx.x;
    if (i < total4) out[i] = __ldg(&bias[i & (FEAT / 4 - 1)]);
}

// Weighted segment-sum over sorted segment_ids.
// 16-lane groups own 64-edge chunks; lane l accumulates features [4l,4l+4).
// Loads for 4 edges are front-batched (high MLP) before any flush branch.
// Interior segments (fully inside a chunk) -> single STG.128 of acc+bias.
// Boundary segments (may be shared with neighbor chunks) -> atomicAdd.
__global__ void __launch_bounds__(THREADS)
segsum_kernel(const float4* __restrict__ feats,   // [E,16] float4 view of [E,64]
              const float*  __restrict__ attn,    // [E]
              const int*    __restrict__ seg,     // [E] sorted
              float* __restrict__ out,            // [N,64] (pre-set to bias)
              const float4* __restrict__ bias4,   // [16]
              int n_edges) {
    int row  = blockIdx.x * ROWS_PER_BLOCK + (threadIdx.x >> 4);
    int lane = threadIdx.x & 15;

    int e0 = row * EPR;
    if (e0 >= n_edges) return;
    int e_end = e0 + EPR;
    if (e_end > n_edges) e_end = n_edges;

    float4 bia = __ldg(&bias4[lane]);
    float4 acc = make_float4(0.f, 0.f, 0.f, 0.f);
    int  cur   = __ldg(&seg[e0]);
    bool first = true;   // current segment may have started in a previous chunk

    int e = e0;
    for (; e + 4 <= e_end; e += 4) {
        // ---- load phase: 12 independent LDGs, no control flow ----
        int   s0 = __ldg(&seg[e + 0]), s1 = __ldg(&seg[e + 1]);
        int   s2 = __ldg(&seg[e + 2]), s3 = __ldg(&seg[e + 3]);
        float a0 = __ldg(&attn[e + 0]), a1 = __ldg(&attn[e + 1]);
        float a2 = __ldg(&attn[e + 2]), a3 = __ldg(&attn[e + 3]);
        float4 f0 = __ldg(&feats[(size_t)(e + 0) * 16 + lane]);
        float4 f1 = __ldg(&feats[(size_t)(e + 1) * 16 + lane]);
        float4 f2 = __ldg(&feats[(size_t)(e + 2) * 16 + lane]);
        float4 f3 = __ldg(&feats[(size_t)(e + 3) * 16 + lane]);

        // ---- process phase ----
        #define STEP(S, A, F)                                                  \
        do {                                                                   \
            if (S != cur) {                                                    \
                if (first) {                                                   \
                    float* o = out + (size_t)cur * FEAT + lane * 4;            \
                    atomicAdd(o + 0, acc.x); atomicAdd(o + 1, acc.y);          \
                    atomicAdd(o + 2, acc.z); atomicAdd(o + 3, acc.w);          \
                } else {                                                       \
                    float4 v = make_float4(acc.x + bia.x, acc.y + bia.y,       \
                                           acc.z + bia.z, acc.w + bia.w);      \
                    ((float4*)(out + (size_t)cur * FEAT))[lane] = v;           \
                }                                                              \
                first = false;                                                 \
                acc = make_float4(0.f, 0.f, 0.f, 0.f);                         \
                cur = S;                                                       \
            }                                                                  \
            acc.x = fmaf(A, F.x, acc.x); acc.y = fmaf(A, F.y, acc.y);          \
            acc.z = fmaf(A, F.z, acc.z); acc.w = fmaf(A, F.w, acc.w);          \
        } while (0)

        STEP(s0, a0, f0);
        STEP(s1, a1, f1);
        STEP(s2, a2, f2);
        STEP(s3, a3, f3);
    }
    // scalar tail (only when n_edges % 4 != 0 within last chunk)
    for (; e < e_end; ++e) {
        int   s = __ldg(&seg[e]);
        float a = __ldg(&attn[e]);
        float4 f = __ldg(&feats[(size_t)e * 16 + lane]);
        STEP(s, a, f);
    }
    #undef STEP

    // final flush: segment may continue into the next chunk
    bool tail_shared = (e_end < n_edges) && (__ldg(&seg[e_end]) == cur);
    if (first || tail_shared) {
        float* o = out + (size_t)cur * FEAT + lane * 4;
        atomicAdd(o + 0, acc.x); atomicAdd(o + 1, acc.y);
        atomicAdd(o + 2, acc.z); atomicAdd(o + 3, acc.w);
    } else {
        float4 v = make_float4(acc.x + bia.x, acc.y + bia.y,
                               acc.z + bia.z, acc.w + bia.w);
        ((float4*)(out + (size_t)cur * FEAT))[lane] = v;
    }
}

extern "C" void kernel_launch(void* const* d_in, const int* in_sizes, int n_in,
                              void* d_out, int out_size) {
    // metadata order: nodes[0] (unused), neighbor_feats[1], attention[2],
    //                 bias[3], segment_ids[4]
    const float* feats = (const float*)d_in[1];
    const float* attn  = (const float*)d_in[2];
    const float* bias  = (const float*)d_in[3];
    const int*   seg   = (const int*)d_in[4];
    float* out = (float*)d_out;

    int n_edges = in_sizes[2];          // attention element count = E

    // 1) out = bias (vectorized broadcast)
    {
        int total4 = out_size / 4;      // N * FEAT / 4
        int blocks = (total4 + THREADS - 1) / THREADS;
        init_out_kernel<<<blocks, THREADS>>>((float4*)out, (const float4*)bias,
                                             total4);
    }

    // 2) weighted segment-sum, boundary-only atomics, interior plain stores
    {
        int n_rows = (n_edges + EPR - 1) / EPR;
        int blocks = (n_rows + ROWS_PER_BLOCK - 1) / ROWS_PER_BLOCK;
        segsum_kernel<<<blocks, THREADS>>>((const float4*)feats, attn, seg, out,
                                           (const float4*)bias, n_edges);
    }
}